// round 8
// baseline (speedup 1.0000x reference)
#include <cuda_runtime.h>
#include <cstdint>

// ============================================================================
// DifferentiableXGB — base-arch (compute_103), int8 IMMA m16n8k32 version.
// split[B,416pad] = x[32768,1024] @ W1^T.
// 256 CTAs (128-row x tiles), 256 threads (warpM 0..3 x warpN 0..1, j=2).
// Phase 0: quantize x tile per (row, k128-chunk) into RESIDENT smem (8 chunks,
// 128 KB) — x read once, no re-read across the two tree-group passes.
// Passes stream W int8 (per-row scales) via triple-buffered cp.async.
// s32 accumulate per chunk -> fp32 dequant with x chunk scale; W scale folded
// in the fused tree epilogue. FC in-kernel. 2 kernels total.
// ============================================================================

static constexpr int BTOT  = 32768;
static constexpr int Dk    = 1024;
static constexpr int NPAD  = 416;    // 400 cols padded (pad trees: fw=0, sw=0)
static constexpr int BN    = 208;    // cols per pass (52 trees, 13 n8-blocks/warpN)
static constexpr int BM    = 128;
static constexpr int NVC   = 16;     // 2 passes x 8 chunks of k=128
static constexpr int NT    = 256;

// smem byte offsets
static constexpr int S_BIAS = 0;         // 416 f
static constexpr int S_SW   = 1664;      // 416 f (W row scales)
static constexpr int S_FW   = 3328;      // 104 f + fc_w[8] + fc_b[2]
static constexpr int S_RED  = 3840;      // 512 f
static constexpr int S_SXS  = 5888;      // 8*128 f (x chunk scales)
static constexpr int S_A    = 10240;     // 8 chunks * 16384 = 131072 (resident)
static constexpr int S_B    = 141312;    // 3 * 26624 (triple-buffered W tiles)
static constexpr int S_TOTAL= 221184;

#define SW(o) ((o) ^ (((o) >> 3) & 0x70))

__device__ __align__(16) int8_t g_Wq[NPAD * Dk];   // 426 KB int8 W
__device__ float g_Ws[NPAD];                        // per-row W scales

// ---------------- asm helpers (all base-arch) ----------------
__device__ __forceinline__ uint32_t smem_u32(const void* p) {
    uint32_t a;
    asm("{ .reg .u64 t; cvta.to.shared.u64 t, %1; cvt.u32.u64 %0, t; }" : "=r"(a) : "l"(p));
    return a;
}
__device__ __forceinline__ void ldsm_x4(uint32_t (&r)[4], uint32_t addr) {
    asm volatile("ldmatrix.sync.aligned.m8n8.x4.shared.b16 {%0,%1,%2,%3}, [%4];"
                 : "=r"(r[0]), "=r"(r[1]), "=r"(r[2]), "=r"(r[3]) : "r"(addr));
}
__device__ __forceinline__ void ldsm_x2(uint32_t (&r)[2], uint32_t addr) {
    asm volatile("ldmatrix.sync.aligned.m8n8.x2.shared.b16 {%0,%1}, [%2];"
                 : "=r"(r[0]), "=r"(r[1]) : "r"(addr));
}
__device__ __forceinline__ void imma_acc(int (&c)[4], const uint32_t (&a)[4],
                                         uint32_t b0, uint32_t b1) {
    asm volatile("mma.sync.aligned.m16n8k32.row.col.s32.s8.s8.s32 "
                 "{%0,%1,%2,%3}, {%4,%5,%6,%7}, {%8,%9}, {%0,%1,%2,%3};"
                 : "+r"(c[0]), "+r"(c[1]), "+r"(c[2]), "+r"(c[3])
                 : "r"(a[0]), "r"(a[1]), "r"(a[2]), "r"(a[3]), "r"(b0), "r"(b1));
}
__device__ __forceinline__ void imma_zero(int (&c)[4], const uint32_t (&a)[4],
                                          uint32_t b0, uint32_t b1) {
    asm volatile("mma.sync.aligned.m16n8k32.row.col.s32.s8.s8.s32 "
                 "{%0,%1,%2,%3}, {%4,%5,%6,%7}, {%8,%9}, {%10,%10,%10,%10};"
                 : "=r"(c[0]), "=r"(c[1]), "=r"(c[2]), "=r"(c[3])
                 : "r"(a[0]), "r"(a[1]), "r"(a[2]), "r"(a[3]), "r"(b0), "r"(b1),
                   "r"(0));
}
__device__ __forceinline__ void cp16(uint32_t dst, const void* src) {
    asm volatile("cp.async.cg.shared.global [%0], [%1], 16;" :: "r"(dst), "l"(src));
}
__device__ __forceinline__ float sig_t(float v) {   // sigmoid via 1 MUFU (tanh)
    float t;
    asm("tanh.approx.f32 %0, %1;" : "=f"(t) : "f"(v * 0.5f));
    return fmaf(t, 0.5f, 0.5f);
}
// pack 4 floats*inv -> 4 int8 (bytes little-endian v0..v3).
// cvt.pack with sub-16-bit convert type REQUIRES the 4-operand form (c operand).
__device__ __forceinline__ uint32_t q4(float4 v, float inv) {
    int v0 = __float2int_rn(v.x * inv), v1 = __float2int_rn(v.y * inv);
    int v2 = __float2int_rn(v.z * inv), v3 = __float2int_rn(v.w * inv);
    uint32_t t, p;
    asm("cvt.pack.sat.s8.s32.b32 %0, %1, %2, %3;" : "=r"(t) : "r"(v3), "r"(v2), "r"(0));
    asm("cvt.pack.sat.s8.s32.b32 %0, %1, %2, %3;" : "=r"(p) : "r"(v1), "r"(v0), "r"(t));
    return p;
}

// ---------------- kernel 1: quantize W1 (fp32 -> int8 + per-row scale) ------
__global__ void xgb_quant_w(const float* __restrict__ W1) {
    __shared__ float wmax[4];
    const int row = blockIdx.x, t = threadIdx.x;
    const int lane = t & 31, w = t >> 5;
    float4 v0 = make_float4(0.f, 0.f, 0.f, 0.f), v1 = v0;
    if (row < 400) {
        const float* src = W1 + (size_t)row * Dk + t * 8;
        v0 = *reinterpret_cast<const float4*>(src);
        v1 = *reinterpret_cast<const float4*>(src + 4);
    }
    float m = fmaxf(fmaxf(fmaxf(fabsf(v0.x), fabsf(v0.y)), fmaxf(fabsf(v0.z), fabsf(v0.w))),
                    fmaxf(fmaxf(fabsf(v1.x), fabsf(v1.y)), fmaxf(fabsf(v1.z), fabsf(v1.w))));
    #pragma unroll
    for (int s = 16; s > 0; s >>= 1) m = fmaxf(m, __shfl_xor_sync(~0u, m, s));
    if (lane == 0) wmax[w] = m;
    __syncthreads();
    m = fmaxf(fmaxf(wmax[0], wmax[1]), fmaxf(wmax[2], wmax[3]));
    const float mx = fmaxf(m, 1e-20f);
    const float inv = 127.0f / mx;
    uint2 o;
    o.x = q4(v0, inv);
    o.y = q4(v1, inv);
    *reinterpret_cast<uint2*>(g_Wq + (size_t)row * Dk + t * 8) = o;
    if (t == 0) g_Ws[row] = (row < 400) ? mx * (1.0f / 127.0f) : 0.0f;
}

// ---------------- kernel 2: GEMM + fused tree epilogue + FC -----------------
__global__ void __launch_bounds__(NT, 1)
xgb_main(const float* __restrict__ x, const float* __restrict__ b1,
         const float* __restrict__ fw, const float* __restrict__ fcw,
         const float* __restrict__ fcb, float* __restrict__ out) {
    extern __shared__ char smem[];
    const uint32_t smb = smem_u32(smem);
    const int tid  = threadIdx.x;
    const int lane = tid & 31;
    const int wid  = tid >> 5;
    const int warpM = wid & 3, warpN = wid >> 2;   // 4 x 2
    const int row0  = blockIdx.x * BM;
    const int q  = lane & 3;
    const int rq = lane >> 2;

    // constants to smem
    float* bias_sm = reinterpret_cast<float*>(smem + S_BIAS);
    float* sw_sm   = reinterpret_cast<float*>(smem + S_SW);
    float* fw_sm   = reinterpret_cast<float*>(smem + S_FW);
    float* sxs_sm  = reinterpret_cast<float*>(smem + S_SXS);
    for (int i = tid; i < NPAD; i += NT) {
        bias_sm[i] = (i < 400) ? b1[i] : 0.0f;
        sw_sm[i]   = g_Ws[i];
    }
    if (tid < 104) fw_sm[tid] = (tid < 100) ? fw[tid] : 0.0f;
    if (tid < 8)   fw_sm[104 + tid] = fcw[tid];
    if (tid < 2)   fw_sm[112 + tid] = fcb[tid];

    // ---- prologue: start streaming B(0), B(1) before x quantization ----
    {
        const int8_t* ws0 = g_Wq;                 // pass 0, chunk 0
        for (int i = tid; i < BN * 8; i += NT) {
            const int row = i >> 3, c16 = i & 7;
            cp16(smb + S_B + SW((uint32_t)(row * 128 + c16 * 16)),
                 ws0 + (size_t)row * Dk + c16 * 16);
        }
        asm volatile("cp.async.commit_group;" ::: "memory");
        const int8_t* ws1 = g_Wq + 128;           // pass 0, chunk 1
        for (int i = tid; i < BN * 8; i += NT) {
            const int row = i >> 3, c16 = i & 7;
            cp16(smb + S_B + 26624 + SW((uint32_t)(row * 128 + c16 * 16)),
                 ws1 + (size_t)row * Dk + c16 * 16);
        }
        asm volatile("cp.async.commit_group;" ::: "memory");
    }

    // ---- phase 0: quantize x tile into resident A smem (8 chunks) ----
    {
        const float* xr = x + (size_t)row0 * Dk;
        for (int it = 0; it < 16; ++it) {
            const int row = wid + it * 8;          // warp owns row
            const float* xp = xr + (size_t)row * Dk + lane * 4;
            float4 v[8];
            #pragma unroll
            for (int c2 = 0; c2 < 8; ++c2)
                v[c2] = *reinterpret_cast<const float4*>(xp + c2 * 128);
            float m[8];
            #pragma unroll
            for (int c2 = 0; c2 < 8; ++c2)
                m[c2] = fmaxf(fmaxf(fabsf(v[c2].x), fabsf(v[c2].y)),
                              fmaxf(fabsf(v[c2].z), fabsf(v[c2].w)));
            #pragma unroll
            for (int s = 16; s > 0; s >>= 1) {
                #pragma unroll
                for (int c2 = 0; c2 < 8; ++c2)
                    m[c2] = fmaxf(m[c2], __shfl_xor_sync(~0u, m[c2], s));
            }
            #pragma unroll
            for (int c2 = 0; c2 < 8; ++c2) {
                const float mx = fmaxf(m[c2], 1e-20f);
                const uint32_t p = q4(v[c2], 127.0f / mx);
                *reinterpret_cast<uint32_t*>(
                    smem + S_A + c2 * 16384 + SW((uint32_t)(row * 128 + lane * 4))) = p;
                if (lane == 0) sxs_sm[c2 * 128 + row] = mx * (1.0f / 127.0f);
            }
        }
    }

    float facc[2][13][4];
    #pragma unroll
    for (int j = 0; j < 2; ++j)
        #pragma unroll
        for (int b = 0; b < 13; ++b)
            #pragma unroll
            for (int e = 0; e < 4; ++e) facc[j][b][e] = 0.0f;

    float wac[4][2] = {{0.f,0.f},{0.f,0.f},{0.f,0.f},{0.f,0.f}};

    // ---- main loop over 16 virtual chunks (2 passes x 8) ----
    for (int vc = 0; vc < NVC; ++vc) {
        const int c = vc & 7;
        const uint32_t sA = S_A + c * 16384;
        const uint32_t sB = S_B + (vc % 3) * 26624;
        if (vc < NVC - 1) {
            asm volatile("cp.async.wait_group 1;" ::: "memory");
        } else {
            asm volatile("cp.async.wait_group 0;" ::: "memory");
        }
        __syncthreads();    // B(vc) ready; phase-0/STS visible; compute(vc-1) done

        if (vc + 2 < NVC) {   // prefetch B(vc+2) into buffer (vc+2)%3 (read last at vc-1)
            const int v2 = vc + 2;
            const uint32_t sBn = S_B + (v2 % 3) * 26624;
            const int8_t* ws = g_Wq + (size_t)((v2 >> 3) * BN) * Dk + (v2 & 7) * 128;
            for (int i = tid; i < BN * 8; i += NT) {
                const int row = i >> 3, c16 = i & 7;
                cp16(smb + sBn + SW((uint32_t)(row * 128 + c16 * 16)),
                     ws + (size_t)row * Dk + c16 * 16);
            }
            asm volatile("cp.async.commit_group;" ::: "memory");
        }

        // x chunk scales for this thread's 4 rows
        float sxv[2][2];
        #pragma unroll
        for (int j = 0; j < 2; ++j) {
            sxv[j][0] = sxs_sm[c * 128 + warpM * 32 + j * 16 + rq];
            sxv[j][1] = sxs_sm[c * 128 + warpM * 32 + j * 16 + rq + 8];
        }

        // A fragments for all 4 k32-steps
        uint32_t a[2][4][4];
        #pragma unroll
        for (int j = 0; j < 2; ++j)
            #pragma unroll
            for (int ks = 0; ks < 4; ++ks) {
                const uint32_t off = (uint32_t)((warpM * 32 + j * 16 + (lane & 15)) * 128
                                     + ks * 32 + ((lane >> 4) << 4));
                ldsm_x4(a[j][ks], smb + sA + SW(off));
            }

        // 6 block-pairs + tail, accumulate s32 over the chunk, then dequant
        #pragma unroll
        for (int p = 0; p < 6; ++p) {
            uint32_t bq[4][4];
            #pragma unroll
            for (int ks = 0; ks < 4; ++ks) {
                const uint32_t rowb = (uint32_t)(warpN * 104 + p * 16 + (lane & 7)
                                     + ((lane >> 4) << 3));
                const uint32_t off = rowb * 128 + ks * 32 + (((lane >> 3) & 1) << 4);
                ldsm_x4(bq[ks], smb + sB + SW(off));
            }
            int d[2][2][4];
            #pragma unroll
            for (int ks = 0; ks < 4; ++ks) {
                #pragma unroll
                for (int j = 0; j < 2; ++j) {
                    if (ks == 0) {
                        imma_zero(d[j][0], a[j][0], bq[0][0], bq[0][1]);
                        imma_zero(d[j][1], a[j][0], bq[0][2], bq[0][3]);
                    } else {
                        imma_acc(d[j][0], a[j][ks], bq[ks][0], bq[ks][1]);
                        imma_acc(d[j][1], a[j][ks], bq[ks][2], bq[ks][3]);
                    }
                }
            }
            #pragma unroll
            for (int j = 0; j < 2; ++j)
                #pragma unroll
                for (int blk = 0; blk < 2; ++blk) {
                    facc[j][2*p+blk][0] = fmaf((float)d[j][blk][0], sxv[j][0], facc[j][2*p+blk][0]);
                    facc[j][2*p+blk][1] = fmaf((float)d[j][blk][1], sxv[j][0], facc[j][2*p+blk][1]);
                    facc[j][2*p+blk][2] = fmaf((float)d[j][blk][2], sxv[j][1], facc[j][2*p+blk][2]);
                    facc[j][2*p+blk][3] = fmaf((float)d[j][blk][3], sxv[j][1], facc[j][2*p+blk][3]);
                }
        }
        {   // tail block 12
            uint32_t bt[4][2];
            #pragma unroll
            for (int ks = 0; ks < 4; ++ks) {
                const uint32_t rowb = (uint32_t)(warpN * 104 + 96 + (lane & 7));
                const uint32_t off = rowb * 128 + ks * 32 + (((lane >> 3) & 1) << 4);
                ldsm_x2(bt[ks], smb + sB + SW(off));
            }
            int dt[2][4];
            #pragma unroll
            for (int ks = 0; ks < 4; ++ks)
                #pragma unroll
                for (int j = 0; j < 2; ++j) {
                    if (ks == 0) imma_zero(dt[j], a[j][0], bt[0][0], bt[0][1]);
                    else         imma_acc(dt[j], a[j][ks], bt[ks][0], bt[ks][1]);
                }
            #pragma unroll
            for (int j = 0; j < 2; ++j) {
                facc[j][12][0] = fmaf((float)dt[j][0], sxv[j][0], facc[j][12][0]);
                facc[j][12][1] = fmaf((float)dt[j][1], sxv[j][0], facc[j][12][1]);
                facc[j][12][2] = fmaf((float)dt[j][2], sxv[j][1], facc[j][12][2]);
                facc[j][12][3] = fmaf((float)dt[j][3], sxv[j][1], facc[j][12][3]);
            }
        }

        // ---- end of pass: fold trees into wac, reset facc ----
        if (c == 7) {
            const int g = vc >> 3;
            #pragma unroll
            for (int j = 0; j < 2; ++j)
                #pragma unroll
                for (int b = 0; b < 13; ++b) {
                    const int cg = g * BN + warpN * 104 + b * 8 + q * 2;
                    const float bias0 = bias_sm[cg], bias1 = bias_sm[cg + 1];
                    const float sw0 = sw_sm[cg], sw1 = sw_sm[cg + 1];
                    const float fwv = fw_sm[cg >> 2];
                    #pragma unroll
                    for (int h = 0; h < 2; ++h) {
                        const float s0 = fmaf(facc[j][b][2*h],     sw0, bias0);
                        const float s1 = fmaf(facc[j][b][2*h + 1], sw1, bias1);
                        const float sp = s0 + s1;
                        const float S  = sp + __shfl_xor_sync(~0u, sp, 1);
                        const float wS = fwv * S;
                        wac[j*2 + h][0] = fmaf(wS, sig_t(s0), wac[j*2 + h][0]);
                        wac[j*2 + h][1] = fmaf(wS, sig_t(s1), wac[j*2 + h][1]);
                    }
                    facc[j][b][0] = facc[j][b][1] = facc[j][b][2] = facc[j][b][3] = 0.0f;
                }
        }
    }

    // ---- combine tree halves within warp (lanes q ^ 2) ----
    #pragma unroll
    for (int s = 0; s < 4; ++s) {
        wac[s][0] += __shfl_xor_sync(~0u, wac[s][0], 2);
        wac[s][1] += __shfl_xor_sync(~0u, wac[s][1], 2);
    }

    // ---- cross-warpN reduction + FC + store (same lane algebra as R3) ----
    float* red = reinterpret_cast<float*>(smem + S_RED);
    if (warpN == 1 && q < 2) {
        #pragma unroll
        for (int s = 0; s < 4; ++s) {
            const int rl = warpM * 32 + (s >> 1) * 16 + (s & 1) * 8 + rq;
            red[rl * 4 + q * 2]     = wac[s][0];
            red[rl * 4 + q * 2 + 1] = wac[s][1];
        }
    }
    __syncthreads();
    if (warpN == 0) {
        const float w00 = fw_sm[104], w01 = fw_sm[105], w02 = fw_sm[106], w03 = fw_sm[107];
        const float w10 = fw_sm[108], w11 = fw_sm[109], w12 = fw_sm[110], w13 = fw_sm[111];
        const float c0  = fw_sm[112], c1  = fw_sm[113];
        #pragma unroll
        for (int s = 0; s < 4; ++s) {
            const int rl = warpM * 32 + (s >> 1) * 16 + (s & 1) * 8 + rq;
            const int ki = (q & 1) * 2;
            const float v0 = wac[s][0] + red[rl * 4 + ki];
            const float v1 = wac[s][1] + red[rl * 4 + ki + 1];
            const float u0 = __shfl_xor_sync(~0u, v0, 1);
            const float u1 = __shfl_xor_sync(~0u, v1, 1);
            if (q == 0) {
                float2 o;
                o.x = c0 + v0 * w00 + v1 * w01 + u0 * w02 + u1 * w03;
                o.y = c1 + v0 * w10 + v1 * w11 + u0 * w12 + u1 * w13;
                *reinterpret_cast<float2*>(out + 2 * (row0 + rl)) = o;
            }
        }
    }
}

// ---------------- launch ----------------------------------------------------
extern "C" void kernel_launch(void* const* d_in, const int* in_sizes, int n_in,
                              void* d_out, int out_size) {
    const float* x   = (const float*)d_in[0];
    const float* W1  = (const float*)d_in[1];
    const float* b1  = (const float*)d_in[2];
    const float* fw  = (const float*)d_in[3];
    const float* fcw = (const float*)d_in[4];
    const float* fcb = (const float*)d_in[5];
    float* out = (float*)d_out;

    cudaFuncSetAttribute(xgb_main, cudaFuncAttributeMaxDynamicSharedMemorySize, S_TOTAL);

    xgb_quant_w<<<NPAD, 128>>>(W1);
    xgb_main<<<BTOT / BM, NT, S_TOTAL>>>(x, b1, fw, fcw, fcb, out);
}

// round 9
// speedup vs baseline: 2.1687x; 2.1687x over previous
#include <cuda_runtime.h>
#include <cuda_bf16.h>
#include <cstdint>

// ============================================================================
// DifferentiableXGB — base-arch (compute_103), single-pass unpadded kernel.
// GEMM: split[B,400] = x[32768,1024] @ W1^T via mma.sync m16n8k16 bf16 (the
// fastest tensor path available: tcgen05 is blocked by the compute_103 PTX
// target; legacy int8/fp8 mma measured slower/imprecise).
// 256 CTAs (one per 128-row x tile), 256 threads: warpM 0..3 (32 rows, j=2) x
// warpN 0..1 (200 cols = 12 ldsm-x4 pairs + 1 x2 block). N=400 exactly — no
// padding. Single pass, 16 k-chunks, double-buffered A (reg->bf16 smem) and
// B (cp.async). Fused tree epilogue + FC in-kernel. 2 kernels total.
// ============================================================================

static constexpr int BTOT  = 32768;
static constexpr int Dk    = 1024;
static constexpr int NCOL  = 400;
static constexpr int BM    = 128;
static constexpr int KC    = 64;     // k-chunk: 64 bf16 = 128B row (SW128)
static constexpr int NCHUNK= 16;
static constexpr int NT    = 256;

// smem byte offsets
static constexpr int S_BIAS = 0;        // 400 f = 1600 B
static constexpr int S_FW   = 1600;     // 100 fw + 8 fcw + 2 fcb = 110 f
static constexpr int S_RED  = 2048;     // 512 f = 2048 B
static constexpr int S_A0   = 8192;     // 128*128B = 16384
static constexpr int S_A1   = 24576;
static constexpr int S_B0   = 40960;    // 400*128B = 51200
static constexpr int S_B1   = 92160;
static constexpr int S_TOTAL= 143360;

#define SW(o) ((o) ^ (((o) >> 3) & 0x70))

__device__ __align__(16) __nv_bfloat16 g_Wbf[NCOL * Dk];   // 800 KB scratch

// ---------------- asm helpers (all base-arch) ----------------
__device__ __forceinline__ uint32_t smem_u32(const void* p) {
    uint32_t a;
    asm("{ .reg .u64 t; cvta.to.shared.u64 t, %1; cvt.u32.u64 %0, t; }" : "=r"(a) : "l"(p));
    return a;
}
__device__ __forceinline__ void ldsm_x4(uint32_t (&r)[4], uint32_t addr) {
    asm volatile("ldmatrix.sync.aligned.m8n8.x4.shared.b16 {%0,%1,%2,%3}, [%4];"
                 : "=r"(r[0]), "=r"(r[1]), "=r"(r[2]), "=r"(r[3]) : "r"(addr));
}
__device__ __forceinline__ void ldsm_x2(uint32_t (&r)[2], uint32_t addr) {
    asm volatile("ldmatrix.sync.aligned.m8n8.x2.shared.b16 {%0,%1}, [%2];"
                 : "=r"(r[0]), "=r"(r[1]) : "r"(addr));
}
__device__ __forceinline__ void mma16816(float (&c)[4], const uint32_t (&a)[4],
                                         uint32_t b0, uint32_t b1) {
    asm volatile("mma.sync.aligned.m16n8k16.row.col.f32.bf16.bf16.f32 "
                 "{%0,%1,%2,%3}, {%4,%5,%6,%7}, {%8,%9}, {%0,%1,%2,%3};"
                 : "+f"(c[0]), "+f"(c[1]), "+f"(c[2]), "+f"(c[3])
                 : "r"(a[0]), "r"(a[1]), "r"(a[2]), "r"(a[3]), "r"(b0), "r"(b1));
}
__device__ __forceinline__ void cp16(uint32_t dst, const void* src) {
    asm volatile("cp.async.cg.shared.global [%0], [%1], 16;" :: "r"(dst), "l"(src));
}
__device__ __forceinline__ float sig_t(float v) {   // sigmoid via 1 MUFU (tanh)
    float t;
    asm("tanh.approx.f32 %0, %1;" : "=f"(t) : "f"(v * 0.5f));
    return fmaf(t, 0.5f, 0.5f);
}

// ---------------- kernel 1: W1 fp32 -> bf16 ------------------
__global__ void xgb_conv_w(const float* __restrict__ W1) {
    int idx = blockIdx.x * 256 + threadIdx.x;      // 400*256 = 102400 uint2
    float4 v = reinterpret_cast<const float4*>(W1)[idx];
    __nv_bfloat162 p0 = __float22bfloat162_rn(make_float2(v.x, v.y));
    __nv_bfloat162 p1 = __float22bfloat162_rn(make_float2(v.z, v.w));
    uint2 o;
    o.x = *reinterpret_cast<uint32_t*>(&p0);
    o.y = *reinterpret_cast<uint32_t*>(&p1);
    reinterpret_cast<uint2*>(g_Wbf)[idx] = o;
}

// ---------------- kernel 2: GEMM + fused tree epilogue + FC -----------------
__global__ void __launch_bounds__(NT, 1)
xgb_main(const float* __restrict__ x, const float* __restrict__ b1,
         const float* __restrict__ fw, const float* __restrict__ fcw,
         const float* __restrict__ fcb, float* __restrict__ out) {
    extern __shared__ char smem[];
    const uint32_t smb = smem_u32(smem);
    const int tid  = threadIdx.x;
    const int lane = tid & 31;
    const int wid  = tid >> 5;
    const int warpM = wid & 3, warpN = wid >> 2;   // 4 x 2
    const int row0  = blockIdx.x * BM;
    const int q  = lane & 3;     // col quad within n8 block
    const int rq = lane >> 2;    // row within 8

    // constants to smem
    float* bias_sm = reinterpret_cast<float*>(smem + S_BIAS);
    float* fw_sm   = reinterpret_cast<float*>(smem + S_FW);
    for (int i = tid; i < NCOL; i += NT) bias_sm[i] = b1[i];
    if (tid < 100) fw_sm[tid] = fw[tid];
    if (tid < 8)   fw_sm[100 + tid] = fcw[tid];
    if (tid < 2)   fw_sm[108 + tid] = fcb[tid];

    // ---- prologue: chunk 0 ----
    float4 av[8];
    const int f4 = tid & 15, rb = tid >> 4;        // 16 float4/row, 16 row-groups
    const float* xb0 = x + (size_t)(row0 + rb) * Dk + f4 * 4;
    #pragma unroll
    for (int r = 0; r < 8; ++r)
        av[r] = *reinterpret_cast<const float4*>(xb0 + (size_t)r * 16 * Dk);
    for (int i = tid; i < NCOL * 8; i += NT) {     // B(0) -> buf0
        const int row = i >> 3, c16 = i & 7;
        const uint32_t off = (uint32_t)(row * 128 + c16 * 16);
        cp16(smb + S_B0 + SW(off), g_Wbf + (size_t)row * Dk + c16 * 8);
    }
    asm volatile("cp.async.commit_group;" ::: "memory");
    #pragma unroll
    for (int r = 0; r < 8; ++r) {                  // A(0) -> buf0
        __nv_bfloat162 p0 = __float22bfloat162_rn(make_float2(av[r].x, av[r].y));
        __nv_bfloat162 p1 = __float22bfloat162_rn(make_float2(av[r].z, av[r].w));
        uint2 val;
        val.x = *reinterpret_cast<uint32_t*>(&p0);
        val.y = *reinterpret_cast<uint32_t*>(&p1);
        const uint32_t off = (uint32_t)((rb + 16 * r) * 128 + f4 * 8);
        *reinterpret_cast<uint2*>(smem + S_A0 + SW(off)) = val;
    }

    float acc[2][25][4];
    #pragma unroll
    for (int j = 0; j < 2; ++j)
        #pragma unroll
        for (int b = 0; b < 25; ++b)
            #pragma unroll
            for (int k = 0; k < 4; ++k) acc[j][b][k] = 0.0f;

    // ---- main K loop (one barrier per chunk, 16 total) ----
    for (int c = 0; c < NCHUNK; ++c) {
        const uint32_t sA = (c & 1) ? S_A1 : S_A0;
        const uint32_t sB = (c & 1) ? S_B1 : S_B0;
        asm volatile("cp.async.wait_group 0;" ::: "memory");
        __syncthreads();                            // buf c ready; c-1 compute done

        if (c + 1 < NCHUNK) {                       // prefetch c+1
            const float* xbn = xb0 + (c + 1) * KC;
            #pragma unroll
            for (int r = 0; r < 8; ++r)
                av[r] = *reinterpret_cast<const float4*>(xbn + (size_t)r * 16 * Dk);
            const uint32_t sBn = (c & 1) ? S_B0 : S_B1;
            const __nv_bfloat16* ws = g_Wbf + (c + 1) * KC;
            for (int i = tid; i < NCOL * 8; i += NT) {
                const int row = i >> 3, c16 = i & 7;
                const uint32_t off = (uint32_t)(row * 128 + c16 * 16);
                cp16(smb + sBn + SW(off), ws + (size_t)row * Dk + c16 * 8);
            }
            asm volatile("cp.async.commit_group;" ::: "memory");
        }

        // compute chunk c
        #pragma unroll
        for (int ks = 0; ks < 4; ++ks) {
            uint32_t a[2][4];
            #pragma unroll
            for (int j = 0; j < 2; ++j) {
                const uint32_t off = (uint32_t)((warpM * 32 + j * 16 + (lane & 15)) * 128
                                     + ks * 32 + ((lane >> 4) << 4));
                ldsm_x4(a[j], smb + sA + SW(off));
            }
            #pragma unroll
            for (int p = 0; p < 12; ++p) {
                uint32_t bq[4];
                const uint32_t rowb = (uint32_t)(warpN * 200 + p * 16 + (lane & 7)
                                     + ((lane >> 4) << 3));
                const uint32_t off = rowb * 128 + ks * 32 + (((lane >> 3) & 1) << 4);
                ldsm_x4(bq, smb + sB + SW(off));
                mma16816(acc[0][2 * p],     a[0], bq[0], bq[1]);
                mma16816(acc[0][2 * p + 1], a[0], bq[2], bq[3]);
                mma16816(acc[1][2 * p],     a[1], bq[0], bq[1]);
                mma16816(acc[1][2 * p + 1], a[1], bq[2], bq[3]);
            }
            {   // last n8 block (24): rows 192..199
                uint32_t b2[2];
                const uint32_t rowb = (uint32_t)(warpN * 200 + 192 + (lane & 7));
                const uint32_t off = rowb * 128 + ks * 32 + (((lane >> 3) & 1) << 4);
                ldsm_x2(b2, smb + sB + SW(off));
                mma16816(acc[0][24], a[0], b2[0], b2[1]);
                mma16816(acc[1][24], a[1], b2[0], b2[1]);
            }
        }

        if (c + 1 < NCHUNK) {
            // store A(c+1) into the buffer last read at chunk c-1 — safe:
            // every warp passed this chunk's barrier, so compute(c-1) is done.
            const uint32_t sAn = (c & 1) ? S_A0 : S_A1;
            #pragma unroll
            for (int r = 0; r < 8; ++r) {
                __nv_bfloat162 p0 = __float22bfloat162_rn(make_float2(av[r].x, av[r].y));
                __nv_bfloat162 p1 = __float22bfloat162_rn(make_float2(av[r].z, av[r].w));
                uint2 val;
                val.x = *reinterpret_cast<uint32_t*>(&p0);
                val.y = *reinterpret_cast<uint32_t*>(&p1);
                const uint32_t off = (uint32_t)((rb + 16 * r) * 128 + f4 * 8);
                *reinterpret_cast<uint2*>(smem + sAn + SW(off)) = val;
            }
        }
    }

    // ---- fused tree epilogue: trees -> weighted[row, 0..3] ----
    float wac[4][2] = {{0.f,0.f},{0.f,0.f},{0.f,0.f},{0.f,0.f}};
    #pragma unroll
    for (int j = 0; j < 2; ++j) {
        #pragma unroll
        for (int b = 0; b < 25; ++b) {
            const int cg = warpN * 200 + b * 8 + q * 2;
            const float bias0 = bias_sm[cg], bias1 = bias_sm[cg + 1];
            const float fwv = fw_sm[cg >> 2];
            #pragma unroll
            for (int h = 0; h < 2; ++h) {
                const float s0 = acc[j][b][2 * h]     + bias0;
                const float s1 = acc[j][b][2 * h + 1] + bias1;
                const float sp = s0 + s1;
                const float S  = sp + __shfl_xor_sync(0xffffffffu, sp, 1);
                const float wS = fwv * S;
                wac[j * 2 + h][0] = fmaf(wS, sig_t(s0), wac[j * 2 + h][0]);
                wac[j * 2 + h][1] = fmaf(wS, sig_t(s1), wac[j * 2 + h][1]);
            }
        }
    }
    // combine tree halves within warp (lanes q ^ 2)
    #pragma unroll
    for (int s = 0; s < 4; ++s) {
        wac[s][0] += __shfl_xor_sync(0xffffffffu, wac[s][0], 2);
        wac[s][1] += __shfl_xor_sync(0xffffffffu, wac[s][1], 2);
    }

    // ---- cross-warpN reduction + FC + store ----
    float* red = reinterpret_cast<float*>(smem + S_RED);
    if (warpN == 1 && q < 2) {
        #pragma unroll
        for (int s = 0; s < 4; ++s) {
            const int rl = warpM * 32 + (s >> 1) * 16 + (s & 1) * 8 + rq;
            red[rl * 4 + q * 2]     = wac[s][0];
            red[rl * 4 + q * 2 + 1] = wac[s][1];
        }
    }
    __syncthreads();
    if (warpN == 0) {
        const float w00 = fw_sm[100], w01 = fw_sm[101], w02 = fw_sm[102], w03 = fw_sm[103];
        const float w10 = fw_sm[104], w11 = fw_sm[105], w12 = fw_sm[106], w13 = fw_sm[107];
        const float c0  = fw_sm[108], c1  = fw_sm[109];
        #pragma unroll
        for (int s = 0; s < 4; ++s) {
            const int rl = warpM * 32 + (s >> 1) * 16 + (s & 1) * 8 + rq;
            const int ki = (q & 1) * 2;
            const float v0 = wac[s][0] + red[rl * 4 + ki];
            const float v1 = wac[s][1] + red[rl * 4 + ki + 1];
            // partner lane (q^1) holds the other k-pair
            const float u0 = __shfl_xor_sync(0xffffffffu, v0, 1);
            const float u1 = __shfl_xor_sync(0xffffffffu, v1, 1);
            if (q == 0) {
                // k0=v0 k1=v1 k2=u0 k3=u1
                float2 o;
                o.x = c0 + v0 * w00 + v1 * w01 + u0 * w02 + u1 * w03;
                o.y = c1 + v0 * w10 + v1 * w11 + u0 * w12 + u1 * w13;
                *reinterpret_cast<float2*>(out + 2 * (row0 + rl)) = o;
            }
        }
    }
}

// ---------------- launch ----------------------------------------------------
extern "C" void kernel_launch(void* const* d_in, const int* in_sizes, int n_in,
                              void* d_out, int out_size) {
    const float* x   = (const float*)d_in[0];
    const float* W1  = (const float*)d_in[1];
    const float* b1  = (const float*)d_in[2];
    const float* fw  = (const float*)d_in[3];
    const float* fcw = (const float*)d_in[4];
    const float* fcb = (const float*)d_in[5];
    float* out = (float*)d_out;

    cudaFuncSetAttribute(xgb_main, cudaFuncAttributeMaxDynamicSharedMemorySize, S_TOTAL);

    xgb_conv_w<<<400, 256>>>(W1);
    xgb_main<<<BTOT / BM, NT, S_TOTAL>>>(x, b1, fw, fcw, fcb, out);
}

// round 10
// speedup vs baseline: 2.4016x; 1.1074x over previous
#include <cuda_runtime.h>
#include <cuda_bf16.h>
#include <cstdint>

// ============================================================================
// DifferentiableXGB — base-arch (compute_103), 512-thread / 56-acc version.
// GEMM: split[B,448pad] = x[32768,1024] @ W1^T via mma.sync m16n8k16 bf16.
// 256 CTAs (one per 128-row x tile), 16 warps = warpM 0..3 (32 rows, j=2) x
// warpN 0..3 (56 cols = 3 ldsm-x4 + 1 ldsm-x2). Two passes (BN=224) so the
// accumulator footprint is 56 regs/thread -> 4 warps/SMSP with NO spills
// (the first config in this series to exceed 2 warps/SMSP spill-free).
// Fused tree epilogue + FC in-kernel. 2 kernels total (conv_w + main).
// ============================================================================

static constexpr int BTOT  = 32768;
static constexpr int Dk    = 1024;
static constexpr int NPAD  = 448;    // 400 cols padded (pad trees: fw=0, bias=0)
static constexpr int BN    = 224;    // cols per pass (56 per warpN)
static constexpr int BM    = 128;
static constexpr int KC    = 64;     // k-chunk: 64 bf16 = 128B row (SW128)
static constexpr int NCHUNK= 16;
static constexpr int NT    = 512;

// smem byte offsets (A/B bases 1024-aligned for SW128)
static constexpr int S_BIAS = 0;        // 448 f = 1792 B
static constexpr int S_FW   = 1792;     // 112 fw + 8 fcw + 2 fcb = 122 f
static constexpr int S_RED  = 2432;     // 3 slabs * 512 f = 6144 B
static constexpr int S_A0   = 9216;     // 128*128B = 16384
static constexpr int S_A1   = 25600;
static constexpr int S_B0   = 41984;    // 224*128B = 28672
static constexpr int S_B1   = 70656;
static constexpr int S_TOTAL= 99328;

#define SW(o) ((o) ^ (((o) >> 3) & 0x70))

__device__ __align__(16) __nv_bfloat16 g_Wbf[NPAD * Dk];   // 896 KB scratch

// ---------------- asm helpers (all base-arch) ----------------
__device__ __forceinline__ uint32_t smem_u32(const void* p) {
    uint32_t a;
    asm("{ .reg .u64 t; cvta.to.shared.u64 t, %1; cvt.u32.u64 %0, t; }" : "=r"(a) : "l"(p));
    return a;
}
__device__ __forceinline__ void ldsm_x4(uint32_t (&r)[4], uint32_t addr) {
    asm volatile("ldmatrix.sync.aligned.m8n8.x4.shared.b16 {%0,%1,%2,%3}, [%4];"
                 : "=r"(r[0]), "=r"(r[1]), "=r"(r[2]), "=r"(r[3]) : "r"(addr));
}
__device__ __forceinline__ void ldsm_x2(uint32_t (&r)[2], uint32_t addr) {
    asm volatile("ldmatrix.sync.aligned.m8n8.x2.shared.b16 {%0,%1}, [%2];"
                 : "=r"(r[0]), "=r"(r[1]) : "r"(addr));
}
__device__ __forceinline__ void mma16816(float (&c)[4], const uint32_t (&a)[4],
                                         uint32_t b0, uint32_t b1) {
    asm volatile("mma.sync.aligned.m16n8k16.row.col.f32.bf16.bf16.f32 "
                 "{%0,%1,%2,%3}, {%4,%5,%6,%7}, {%8,%9}, {%0,%1,%2,%3};"
                 : "+f"(c[0]), "+f"(c[1]), "+f"(c[2]), "+f"(c[3])
                 : "r"(a[0]), "r"(a[1]), "r"(a[2]), "r"(a[3]), "r"(b0), "r"(b1));
}
__device__ __forceinline__ void cp16(uint32_t dst, const void* src) {
    asm volatile("cp.async.cg.shared.global [%0], [%1], 16;" :: "r"(dst), "l"(src));
}
__device__ __forceinline__ float sig_t(float v) {   // sigmoid via 1 MUFU (tanh)
    float t;
    asm("tanh.approx.f32 %0, %1;" : "=f"(t) : "f"(v * 0.5f));
    return fmaf(t, 0.5f, 0.5f);
}

// ---------------- kernel 1: W1 fp32 -> bf16 (padded to 448 rows) ------------
__global__ void xgb_conv_w(const float* __restrict__ W1) {
    int idx = blockIdx.x * 256 + threadIdx.x;      // 448*256 = 114688 uint2
    uint2 o = make_uint2(0u, 0u);
    if (idx < 102400) {                            // 400*1024/4
        float4 v = reinterpret_cast<const float4*>(W1)[idx];
        __nv_bfloat162 p0 = __float22bfloat162_rn(make_float2(v.x, v.y));
        __nv_bfloat162 p1 = __float22bfloat162_rn(make_float2(v.z, v.w));
        o.x = *reinterpret_cast<uint32_t*>(&p0);
        o.y = *reinterpret_cast<uint32_t*>(&p1);
    }
    reinterpret_cast<uint2*>(g_Wbf)[idx] = o;
}

// ---------------- kernel 2: GEMM + fused tree epilogue + FC -----------------
__global__ void __launch_bounds__(NT, 1)
xgb_main(const float* __restrict__ x, const float* __restrict__ b1,
         const float* __restrict__ fw, const float* __restrict__ fcw,
         const float* __restrict__ fcb, float* __restrict__ out) {
    extern __shared__ char smem[];
    const uint32_t smb = smem_u32(smem);
    const int tid  = threadIdx.x;
    const int lane = tid & 31;
    const int wid  = tid >> 5;
    const int warpM = wid & 3, warpN = wid >> 2;   // 4 x 4
    const int row0  = blockIdx.x * BM;
    const int q  = lane & 3;     // col quad within n8 block
    const int rq = lane >> 2;    // row within 8

    // constants to smem
    float* bias_sm = reinterpret_cast<float*>(smem + S_BIAS);
    float* fw_sm   = reinterpret_cast<float*>(smem + S_FW);
    for (int i = tid; i < NPAD; i += NT) bias_sm[i] = (i < 400) ? b1[i] : 0.0f;
    if (tid < 112) fw_sm[tid] = (tid < 100) ? fw[tid] : 0.0f;
    if (tid < 8)   fw_sm[112 + tid] = fcw[tid];
    if (tid < 2)   fw_sm[120 + tid] = fcb[tid];

    // x staging: 2048 float4 per chunk over 512 threads -> 4 each
    const int f4 = tid & 15;                  // float4 within row
    const int rb = tid >> 4;                  // 0..31; rows rb + 32*r
    const float* xb0 = x + (size_t)(row0 + rb) * Dk + f4 * 4;

    float wac[4][2] = {{0.f,0.f},{0.f,0.f},{0.f,0.f},{0.f,0.f}};

    for (int g = 0; g < 2; ++g) {
        const __nv_bfloat16* wsrc = g_Wbf + (size_t)g * BN * Dk;

        // ---- prologue: chunk 0 ----
        float4 av[4];
        #pragma unroll
        for (int r = 0; r < 4; ++r)
            av[r] = *reinterpret_cast<const float4*>(xb0 + (size_t)r * 32 * Dk);
        for (int i = tid; i < BN * 8; i += NT) {           // B(0) -> buf0
            const int row = i >> 3, c16 = i & 7;
            const uint32_t off = (uint32_t)(row * 128 + c16 * 16);
            cp16(smb + S_B0 + SW(off), wsrc + (size_t)row * Dk + c16 * 8);
        }
        asm volatile("cp.async.commit_group;" ::: "memory");
        #pragma unroll
        for (int r = 0; r < 4; ++r) {                      // A(0) -> buf0
            __nv_bfloat162 p0 = __float22bfloat162_rn(make_float2(av[r].x, av[r].y));
            __nv_bfloat162 p1 = __float22bfloat162_rn(make_float2(av[r].z, av[r].w));
            uint2 val;
            val.x = *reinterpret_cast<uint32_t*>(&p0);
            val.y = *reinterpret_cast<uint32_t*>(&p1);
            const uint32_t off = (uint32_t)((rb + 32 * r) * 128 + f4 * 8);
            *reinterpret_cast<uint2*>(smem + S_A0 + SW(off)) = val;
        }

        float acc[2][7][4];
        #pragma unroll
        for (int j = 0; j < 2; ++j)
            #pragma unroll
            for (int b = 0; b < 7; ++b)
                #pragma unroll
                for (int k = 0; k < 4; ++k) acc[j][b][k] = 0.0f;

        // ---- main K loop (one barrier per chunk) ----
        for (int c = 0; c < NCHUNK; ++c) {
            const uint32_t sA = (c & 1) ? S_A1 : S_A0;
            const uint32_t sB = (c & 1) ? S_B1 : S_B0;
            asm volatile("cp.async.wait_group 0;" ::: "memory");
            __syncthreads();                                // buf c ready; c-1 compute done

            if (c + 1 < NCHUNK) {                           // prefetch c+1
                const float* xbn = xb0 + (c + 1) * KC;
                #pragma unroll
                for (int r = 0; r < 4; ++r)
                    av[r] = *reinterpret_cast<const float4*>(xbn + (size_t)r * 32 * Dk);
                const uint32_t sBn = (c & 1) ? S_B0 : S_B1;
                const __nv_bfloat16* ws = wsrc + (c + 1) * KC;
                for (int i = tid; i < BN * 8; i += NT) {
                    const int row = i >> 3, c16 = i & 7;
                    const uint32_t off = (uint32_t)(row * 128 + c16 * 16);
                    cp16(smb + sBn + SW(off), ws + (size_t)row * Dk + c16 * 8);
                }
                asm volatile("cp.async.commit_group;" ::: "memory");
            }

            // compute chunk c: 4 ks x (2 a-ldsm, 3 b-ldsm-x4 + 1 b-ldsm-x2, 14 MMA)
            #pragma unroll
            for (int ks = 0; ks < 4; ++ks) {
                uint32_t a[2][4];
                #pragma unroll
                for (int j = 0; j < 2; ++j) {
                    const uint32_t off = (uint32_t)((warpM * 32 + j * 16 + (lane & 15)) * 128
                                         + ks * 32 + ((lane >> 4) << 4));
                    ldsm_x4(a[j], smb + sA + SW(off));
                }
                #pragma unroll
                for (int p = 0; p < 3; ++p) {
                    uint32_t bq[4];
                    const uint32_t rowb = (uint32_t)(warpN * 56 + p * 16 + (lane & 7)
                                         + ((lane >> 4) << 3));
                    const uint32_t off = rowb * 128 + ks * 32 + (((lane >> 3) & 1) << 4);
                    ldsm_x4(bq, smb + sB + SW(off));
                    mma16816(acc[0][2 * p],     a[0], bq[0], bq[1]);
                    mma16816(acc[0][2 * p + 1], a[0], bq[2], bq[3]);
                    mma16816(acc[1][2 * p],     a[1], bq[0], bq[1]);
                    mma16816(acc[1][2 * p + 1], a[1], bq[2], bq[3]);
                }
                {   // tail n8 block (6): rows 48..55 of this warpN's slice
                    uint32_t b2[2];
                    const uint32_t rowb = (uint32_t)(warpN * 56 + 48 + (lane & 7));
                    const uint32_t off = rowb * 128 + ks * 32 + (((lane >> 3) & 1) << 4);
                    ldsm_x2(b2, smb + sB + SW(off));
                    mma16816(acc[0][6], a[0], b2[0], b2[1]);
                    mma16816(acc[1][6], a[1], b2[0], b2[1]);
                }
            }

            if (c + 1 < NCHUNK) {
                // convert A(c+1) into buffer last read at chunk c-1 (safe post-barrier)
                const uint32_t sAn = (c & 1) ? S_A0 : S_A1;
                #pragma unroll
                for (int r = 0; r < 4; ++r) {
                    __nv_bfloat162 p0 = __float22bfloat162_rn(make_float2(av[r].x, av[r].y));
                    __nv_bfloat162 p1 = __float22bfloat162_rn(make_float2(av[r].z, av[r].w));
                    uint2 val;
                    val.x = *reinterpret_cast<uint32_t*>(&p0);
                    val.y = *reinterpret_cast<uint32_t*>(&p1);
                    const uint32_t off = (uint32_t)((rb + 32 * r) * 128 + f4 * 8);
                    *reinterpret_cast<uint2*>(smem + sAn + SW(off)) = val;
                }
            }
        }

        // ---- per-pass epilogue: fold trees into wac ----
        #pragma unroll
        for (int j = 0; j < 2; ++j) {
            #pragma unroll
            for (int b = 0; b < 7; ++b) {
                const int cg = g * BN + warpN * 56 + b * 8 + q * 2;
                const float bias0 = bias_sm[cg], bias1 = bias_sm[cg + 1];
                const float fwv = fw_sm[cg >> 2];
                #pragma unroll
                for (int h = 0; h < 2; ++h) {
                    const float s0 = acc[j][b][2 * h]     + bias0;
                    const float s1 = acc[j][b][2 * h + 1] + bias1;
                    const float sp = s0 + s1;
                    const float S  = sp + __shfl_xor_sync(0xffffffffu, sp, 1);
                    const float wS = fwv * S;
                    wac[j * 2 + h][0] = fmaf(wS, sig_t(s0), wac[j * 2 + h][0]);
                    wac[j * 2 + h][1] = fmaf(wS, sig_t(s1), wac[j * 2 + h][1]);
                }
            }
        }
        // pass boundary: next prologue writes A0/B0, last read at chunk 14 —
        // the chunk-15 barrier (after compute(14)) makes that safe.
    }

    // ---- combine tree halves within warp (lanes q ^ 2) ----
    #pragma unroll
    for (int s = 0; s < 4; ++s) {
        wac[s][0] += __shfl_xor_sync(0xffffffffu, wac[s][0], 2);
        wac[s][1] += __shfl_xor_sync(0xffffffffu, wac[s][1], 2);
    }

    // ---- cross-warpN reduction (warpN 1..3 -> warpN 0) + FC + store ----
    float* red = reinterpret_cast<float*>(smem + S_RED);
    __syncthreads();                 // all compute/ldsm done; order wac stores
    if (warpN > 0 && q < 2) {
        #pragma unroll
        for (int s = 0; s < 4; ++s) {
            const int rl = warpM * 32 + (s >> 1) * 16 + (s & 1) * 8 + rq;
            red[(warpN - 1) * 512 + rl * 4 + q * 2]     = wac[s][0];
            red[(warpN - 1) * 512 + rl * 4 + q * 2 + 1] = wac[s][1];
        }
    }
    __syncthreads();
    if (warpN == 0) {
        const float w00 = fw_sm[112], w01 = fw_sm[113], w02 = fw_sm[114], w03 = fw_sm[115];
        const float w10 = fw_sm[116], w11 = fw_sm[117], w12 = fw_sm[118], w13 = fw_sm[119];
        const float c0  = fw_sm[120], c1  = fw_sm[121];
        #pragma unroll
        for (int s = 0; s < 4; ++s) {
            const int rl = warpM * 32 + (s >> 1) * 16 + (s & 1) * 8 + rq;
            const int ki = (q & 1) * 2;
            float v0 = wac[s][0], v1 = wac[s][1];
            #pragma unroll
            for (int w = 0; w < 3; ++w) {
                v0 += red[w * 512 + rl * 4 + ki];
                v1 += red[w * 512 + rl * 4 + ki + 1];
            }
            // partner lane (q^1) holds the other k-pair
            const float u0 = __shfl_xor_sync(0xffffffffu, v0, 1);
            const float u1 = __shfl_xor_sync(0xffffffffu, v1, 1);
            if (q == 0) {
                // k0=v0 k1=v1 k2=u0 k3=u1
                float2 o;
                o.x = c0 + v0 * w00 + v1 * w01 + u0 * w02 + u1 * w03;
                o.y = c1 + v0 * w10 + v1 * w11 + u0 * w12 + u1 * w13;
                *reinterpret_cast<float2*>(out + 2 * (row0 + rl)) = o;
            }
        }
    }
}

// ---------------- launch ----------------------------------------------------
extern "C" void kernel_launch(void* const* d_in, const int* in_sizes, int n_in,
                              void* d_out, int out_size) {
    const float* x   = (const float*)d_in[0];
    const float* W1  = (const float*)d_in[1];
    const float* b1  = (const float*)d_in[2];
    const float* fw  = (const float*)d_in[3];
    const float* fcw = (const float*)d_in[4];
    const float* fcb = (const float*)d_in[5];
    float* out = (float*)d_out;

    cudaFuncSetAttribute(xgb_main, cudaFuncAttributeMaxDynamicSharedMemorySize, S_TOTAL);

    xgb_conv_w<<<448, 256>>>(W1);
    xgb_main<<<BTOT / BM, NT, S_TOTAL>>>(x, b1, fw, fcw, fcb, out);
}